// round 9
// baseline (speedup 1.0000x reference)
#include <cuda_runtime.h>
#include <math.h>

#define N_VOX (256*256*256)
#define NUM_SHELLS 222
#define NB (2*3*NUM_SHELLS)

// Hermitian-packed: 2 complex volumes (Z = X + iY per batch), two buffers.
// g_F : [batch][z][y][x]   (after pass 1)
// g_F2: [batch][y][z][x]   (after pass 2; z becomes the stride-256 axis)
__device__ float2 g_F [(size_t)2 * N_VOX];
__device__ float2 g_F2[(size_t)2 * N_VOX];
__device__ float  g_acc[NB];
__device__ float2 g_tw[256];   // W256^k

__constant__ float2 TW16C[8] = {
    { 1.0f,           0.0f          },
    { 0.92387953251f, -0.38268343236f },
    { 0.70710678119f, -0.70710678119f },
    { 0.38268343236f, -0.92387953251f },
    { 0.0f,          -1.0f          },
    {-0.38268343236f, -0.92387953251f },
    {-0.70710678119f, -0.70710678119f },
    {-0.92387953251f, -0.38268343236f }
};

__device__ __forceinline__ float2 cmulf(float2 a, float2 b) {
    return make_float2(a.x*b.x - a.y*b.y, a.x*b.y + a.y*b.x);
}

// 16-point radix-2 DIT FFT in registers. Natural in -> natural out.
__device__ __forceinline__ void fft16(float2 v[16]) {
    float2 t;
#define SWP(a,b) { t = v[a]; v[a] = v[b]; v[b] = t; }
    SWP(1,8) SWP(2,4) SWP(3,12) SWP(5,10) SWP(7,14) SWP(11,13)
#undef SWP
#pragma unroll
    for (int st = 0; st < 4; st++) {
        int half = 1 << st;
#pragma unroll
        for (int j = 0; j < 8; j++) {
            int pos = j & (half - 1);
            int i0  = ((j >> st) << (st + 1)) + pos;
            int i1  = i0 + half;
            float2 w = TW16C[pos << (3 - st)];
            float2 b = cmulf(w, v[i1]);
            float2 a = v[i0];
            v[i0] = make_float2(a.x + b.x, a.y + b.y);
            v[i1] = make_float2(a.x - b.x, a.y - b.y);
        }
    }
}

// ---------------------------------------------------------------------------
__global__ void init_kernel() {
    int tid = threadIdx.x;
    for (int i = tid; i < NB; i += blockDim.x) g_acc[i] = 0.0f;
    if (tid < 256) {
        float ang = -6.283185307179586f * (float)tid / 256.0f;
        float s, c;
        sincosf(ang, &s, &c);
        g_tw[tid] = make_float2(c, s);
    }
}

// ---------------------------------------------------------------------------
// Pass 1: x-FFT of Z = X + iY (one complex volume per batch).
// ---------------------------------------------------------------------------
__global__ void __launch_bounds__(256)
fft_x_kernel(const float* __restrict__ X, const float* __restrict__ Y) {
    __shared__ float2 sh[16][16][17];
    __shared__ float2 tws[256];
    int tid = threadIdx.x;
    tws[tid] = g_tw[tid];
    int tt = tid & 15;
    int l  = tid >> 4;
    int line = blockIdx.x * 16 + l;       // 0 .. 131071
    int vol  = line >> 16;                // batch 0/1
    int lin  = line & 65535;
    const float* sx = X + (size_t)vol * N_VOX + (size_t)lin * 256;
    const float* sy = Y + (size_t)vol * N_VOX + (size_t)lin * 256;

    float2 v[16];
#pragma unroll
    for (int i = 0; i < 16; i++)
        v[i] = make_float2(sx[tt + 16*i], sy[tt + 16*i]);
    fft16(v);
    __syncthreads();
#pragma unroll
    for (int k2 = 1; k2 < 16; k2++)
        v[k2] = cmulf(v[k2], tws[tt * k2]);
#pragma unroll
    for (int k2 = 0; k2 < 16; k2++)
        sh[l][tt][k2] = v[k2];
    __syncthreads();
    float2 u[16];
#pragma unroll
    for (int n1 = 0; n1 < 16; n1++)
        u[n1] = sh[l][n1][tt];
    fft16(u);
    float2* dst = g_F + (size_t)vol * N_VOX + (size_t)lin * 256;
#pragma unroll
    for (int k1 = 0; k1 < 16; k1++)
        dst[tt + 16*k1] = u[k1];
}

// ---------------------------------------------------------------------------
// Pass 2: y-FFT. Reads g_F [b][z][y][x] (stride-256 loads),
// writes g_F2 [b][y][z][x] (strided stores, fire-and-forget).
// ---------------------------------------------------------------------------
__global__ void __launch_bounds__(256)
fft_y_kernel() {
    __shared__ float2 sh[16][16][16];
    __shared__ float2 tws[256];
    int tid = threadIdx.x;
    tws[tid] = g_tw[tid];
    int c = tid & 15;
    int t = tid >> 4;
    int b    = blockIdx.x;
    int vol  = b >> 12;
    int rem  = b & 4095;
    int z    = rem >> 4;
    int tile = rem & 15;
    const float2* srcv = g_F  + (size_t)vol * N_VOX + (size_t)z * 65536 + tile * 16;
    float2*       dstv = g_F2 + (size_t)vol * N_VOX + (size_t)z * 256   + tile * 16;

    float2 v[16];
#pragma unroll
    for (int i = 0; i < 16; i++)
        v[i] = srcv[(size_t)(t + 16*i) * 256 + c];
    fft16(v);
    __syncthreads();
#pragma unroll
    for (int k2 = 1; k2 < 16; k2++)
        v[k2] = cmulf(v[k2], tws[t * k2]);
#pragma unroll
    for (int k2 = 0; k2 < 16; k2++)
        sh[t][k2][c] = v[k2];
    __syncthreads();
    float2 u[16];
#pragma unroll
    for (int n1 = 0; n1 < 16; n1++)
        u[n1] = sh[n1][t][c];
    fft16(u);
#pragma unroll
    for (int k1 = 0; k1 < 16; k1++)
        dstv[(size_t)(t + 16*k1) * 65536 + c] = u[k1];
}

// ---------------------------------------------------------------------------
// Pass 3: 512 threads/block. Warps 0-7 z-FFT the direct columns (x,y);
// warps 8-15 simultaneously z-FFT the mirrored columns (xm,ym) and publish
// Fz(-k) to shared in z-layout. Direct half then Hermitian-unpacks and bins
// with warp run-aggregation. Block = (batch, y=0..128, x-tile of 16).
// ---------------------------------------------------------------------------
__global__ void __launch_bounds__(512, 2)
fft_z_reduce_kernel() {
    __shared__ float2 shD[4096];         // direct transpose buffer
    __shared__ float2 shM[4096];         // mirror transpose / z-layout exchange
    __shared__ float2 tws[256];
    __shared__ float  bins[3 * NUM_SHELLS];
    int tid = threadIdx.x;
    if (tid < 256) tws[tid] = g_tw[tid];
    for (int i = tid; i < 3 * NUM_SHELLS; i += 512) bins[i] = 0.0f;

    int half = tid >> 8;                 // 0 = direct, 1 = mirror
    int wt   = tid & 255;
    int c = wt & 15;
    int t = wt >> 4;
    int bI    = blockIdx.x;
    int batch = bI / 2064;
    int rem   = bI % 2064;
    int y     = rem >> 4;                // 0..128
    int tile  = rem & 15;
    int x  = tile * 16 + c;
    int xm = (256 - x) & 255;
    int ym = (256 - y) & 255;
    const float2* base = g_F2 + (size_t)batch * N_VOX;

    // column for this thread: direct (x,y) or mirror (xm,ym)
    int colx = half ? xm : x;
    int coly = half ? ym : y;
    float2* mySh = half ? shM : shD;

    float2 v[16];
#pragma unroll
    for (int i = 0; i < 16; i++)
        v[i] = base[(size_t)coly * 65536 + (size_t)(t + 16*i) * 256 + colx];
    fft16(v);
    __syncthreads();                     // #1: tws + bins ready
#pragma unroll
    for (int k2 = 1; k2 < 16; k2++)
        v[k2] = cmulf(v[k2], tws[t * k2]);
#pragma unroll
    for (int k2 = 0; k2 < 16; k2++)
        mySh[(t * 16 + k2) * 16 + c] = v[k2];
    __syncthreads();                     // #2: transpose data ready
    float2 R[16];
#pragma unroll
    for (int n1 = 0; n1 < 16; n1++)
        R[n1] = mySh[(n1 * 16 + t) * 16 + c];
    fft16(R);                            // R[k1] = Fz(col, z = t + 16*k1)
    __syncthreads();                     // #3: everyone done reading transpose
    if (half) {
        // publish mirror spectrum in z-layout: shM[z*16 + c] = Fz(xm,ym,z)
#pragma unroll
        for (int k1 = 0; k1 < 16; k1++)
            shM[(t + 16*k1) * 16 + c] = R[k1];
    }
    __syncthreads();                     // #4: mirror z-layout ready

    if (!half) {
        // ---- unpack + bin (direct half only) ----
        int fx = (x < 128) ? x : x - 256;
        int fy = (y < 128) ? y : y - 256;
        int rxy = fx*fx + fy*fy;
        // weight category: 0 -> always 2; 1 -> depends on z; 2 -> always 0
        bool y_mid  = (unsigned)(y - 1) < 127u;
        bool x_mid  = (unsigned)(x - 1) < 127u;
        bool x_self = (x == 0) || (x == 128);
        int cat = (y_mid || x_mid) ? 0 : (x_self ? 1 : 2);

        const unsigned FULL = 0xffffffffu;
        int lpos = tid & 15;

#pragma unroll
        for (int k1 = 0; k1 < 16; k1++) {
            int z  = t + 16*k1;
            int zm = (256 - z) & 255;
            float2 P = R[k1];                          // Fz(k)
            float2 Q = shM[zm * 16 + c];               // Fz(-k)
            float Fxr = P.x + Q.x, Fxi = P.y - Q.y;    // 2*Fx
            float Fyr = P.y + Q.y, Fyi = Q.x - P.x;    // 2*Fy
            float fw;
            if (cat == 0) fw = 2.0f;
            else if (cat == 2) fw = 0.0f;
            else {
                bool z_mid  = (unsigned)(z - 1) < 127u;
                bool z_self = (z == 0) || (z == 128);
                fw = z_mid ? 2.0f : (z_self ? 1.0f : 0.0f);
            }
            int fz = (z < 128) ? z : z - 256;
            int bin = (int)sqrtf((float)(rxy + fz*fz));
            float nn = fw * (Fxr*Fyr + Fxi*Fyi);
            float pp = fw * (Fxr*Fxr + Fxi*Fxi);
            float qq = fw * (Fyr*Fyr + Fyi*Fyi);

            // run-aggregation within each 16-lane segment (bin monotone in lpos)
#pragma unroll
            for (int off = 1; off < 16; off <<= 1) {
                int   ob = __shfl_down_sync(FULL, bin, off);
                float on = __shfl_down_sync(FULL, nn,  off);
                float op = __shfl_down_sync(FULL, pp,  off);
                float oq = __shfl_down_sync(FULL, qq,  off);
                if (lpos + off < 16 && ob == bin) { nn += on; pp += op; qq += oq; }
            }
            int pb = __shfl_up_sync(FULL, bin, 1);
            if (lpos == 0 || pb != bin) {
                atomicAdd(&bins[bin],                nn);
                atomicAdd(&bins[NUM_SHELLS   + bin], pp);
                atomicAdd(&bins[2*NUM_SHELLS + bin], qq);
            }
        }
    }
    __syncthreads();                     // #5: bins complete
    float* acc = g_acc + batch * 3 * NUM_SHELLS;
    for (int i = tid; i < 3 * NUM_SHELLS; i += 512)
        atomicAdd(&acc[i], bins[i]);
}

// ---------------------------------------------------------------------------
__global__ void final_kernel(float* __restrict__ out) {
    __shared__ float red[256];
    int tid = threadIdx.x;
    float s = 0.0f;
    for (int i = tid; i < 2 * NUM_SHELLS; i += 256) {
        int bt = i / NUM_SHELLS;
        int sh_ = i % NUM_SHELLS;
        const float* acc = g_acc + bt * 3 * NUM_SHELLS;
        float num = acc[sh_];
        float px  = acc[NUM_SHELLS + sh_];
        float py  = acc[2*NUM_SHELLS + sh_];
        s += num / sqrtf(px * py + 1e-8f);
    }
    red[tid] = s;
    __syncthreads();
    for (int o = 128; o > 0; o >>= 1) {
        if (tid < o) red[tid] += red[tid + o];
        __syncthreads();
    }
    if (tid == 0) out[0] = red[0] / (2.0f * NUM_SHELLS);
}

// ---------------------------------------------------------------------------
extern "C" void kernel_launch(void* const* d_in, const int* in_sizes, int n_in,
                              void* d_out, int out_size) {
    const float* X = (const float*)d_in[0];
    const float* Y = (const float*)d_in[1];

    init_kernel<<<1, 256>>>();
    fft_x_kernel<<<8192, 256>>>(X, Y);      // 2 packed vols * 65536 lines / 16
    fft_y_kernel<<<8192, 256>>>();          // 2 vols * 256 z * 16 tiles
    fft_z_reduce_kernel<<<4128, 512>>>();   // 2 batches * 129 y * 16 tiles
    final_kernel<<<1, 256>>>((float*)d_out);
}

// round 10
// speedup vs baseline: 1.2031x; 1.2031x over previous
#include <cuda_runtime.h>
#include <math.h>

#define N_VOX (256*256*256)
#define NUM_SHELLS 222
#define NB (2*3*NUM_SHELLS)

// Hermitian-packed: 2 complex volumes (Z = X + iY per batch), two buffers.
// g_F : [batch][z][y][x]   (after pass 1)
// g_F2: [batch][y][z][x]   (after pass 2; z becomes the stride-256 axis)
__device__ float2 g_F [(size_t)2 * N_VOX];
__device__ float2 g_F2[(size_t)2 * N_VOX];
__device__ float  g_acc[NB];
__device__ float2 g_tw[256];   // W256^k

__constant__ float2 TW16C[8] = {
    { 1.0f,           0.0f          },
    { 0.92387953251f, -0.38268343236f },
    { 0.70710678119f, -0.70710678119f },
    { 0.38268343236f, -0.92387953251f },
    { 0.0f,          -1.0f          },
    {-0.38268343236f, -0.92387953251f },
    {-0.70710678119f, -0.70710678119f },
    {-0.92387953251f, -0.38268343236f }
};

__device__ __forceinline__ float2 cmulf(float2 a, float2 b) {
    return make_float2(a.x*b.x - a.y*b.y, a.x*b.y + a.y*b.x);
}

// 16-point radix-2 DIT FFT in registers. Natural in -> natural out.
__device__ __forceinline__ void fft16(float2 v[16]) {
    float2 t;
#define SWP(a,b) { t = v[a]; v[a] = v[b]; v[b] = t; }
    SWP(1,8) SWP(2,4) SWP(3,12) SWP(5,10) SWP(7,14) SWP(11,13)
#undef SWP
#pragma unroll
    for (int st = 0; st < 4; st++) {
        int half = 1 << st;
#pragma unroll
        for (int j = 0; j < 8; j++) {
            int pos = j & (half - 1);
            int i0  = ((j >> st) << (st + 1)) + pos;
            int i1  = i0 + half;
            float2 w = TW16C[pos << (3 - st)];
            float2 b = cmulf(w, v[i1]);
            float2 a = v[i0];
            v[i0] = make_float2(a.x + b.x, a.y + b.y);
            v[i1] = make_float2(a.x - b.x, a.y - b.y);
        }
    }
}

// ---------------------------------------------------------------------------
__global__ void init_kernel() {
    int tid = threadIdx.x;
    for (int i = tid; i < NB; i += blockDim.x) g_acc[i] = 0.0f;
    if (tid < 256) {
        float ang = -6.283185307179586f * (float)tid / 256.0f;
        float s, c;
        sincosf(ang, &s, &c);
        g_tw[tid] = make_float2(c, s);
    }
}

// ---------------------------------------------------------------------------
// Pass 1: x-FFT of Z = X + iY (one complex volume per batch).
// ---------------------------------------------------------------------------
__global__ void __launch_bounds__(256)
fft_x_kernel(const float* __restrict__ X, const float* __restrict__ Y) {
    __shared__ float2 sh[16][16][17];
    __shared__ float2 tws[256];
    int tid = threadIdx.x;
    tws[tid] = g_tw[tid];
    int tt = tid & 15;
    int l  = tid >> 4;
    int line = blockIdx.x * 16 + l;       // 0 .. 131071
    int vol  = line >> 16;                // batch 0/1
    int lin  = line & 65535;
    const float* sx = X + (size_t)vol * N_VOX + (size_t)lin * 256;
    const float* sy = Y + (size_t)vol * N_VOX + (size_t)lin * 256;

    float2 v[16];
#pragma unroll
    for (int i = 0; i < 16; i++)
        v[i] = make_float2(sx[tt + 16*i], sy[tt + 16*i]);
    fft16(v);
    __syncthreads();
#pragma unroll
    for (int k2 = 1; k2 < 16; k2++)
        v[k2] = cmulf(v[k2], tws[tt * k2]);
#pragma unroll
    for (int k2 = 0; k2 < 16; k2++)
        sh[l][tt][k2] = v[k2];
    __syncthreads();
    float2 u[16];
#pragma unroll
    for (int n1 = 0; n1 < 16; n1++)
        u[n1] = sh[l][n1][tt];
    fft16(u);
    float2* dst = g_F + (size_t)vol * N_VOX + (size_t)lin * 256;
#pragma unroll
    for (int k1 = 0; k1 < 16; k1++)
        dst[tt + 16*k1] = u[k1];
}

// ---------------------------------------------------------------------------
// Pass 2: y-FFT. Reads g_F [b][z][y][x] (stride-256 loads),
// writes g_F2 [b][y][z][x] (strided stores, fire-and-forget).
// ---------------------------------------------------------------------------
__global__ void __launch_bounds__(256)
fft_y_kernel() {
    __shared__ float2 sh[16][16][16];
    __shared__ float2 tws[256];
    int tid = threadIdx.x;
    tws[tid] = g_tw[tid];
    int c = tid & 15;
    int t = tid >> 4;
    int b    = blockIdx.x;
    int vol  = b >> 12;
    int rem  = b & 4095;
    int z    = rem >> 4;
    int tile = rem & 15;
    const float2* srcv = g_F  + (size_t)vol * N_VOX + (size_t)z * 65536 + tile * 16;
    float2*       dstv = g_F2 + (size_t)vol * N_VOX + (size_t)z * 256   + tile * 16;

    float2 v[16];
#pragma unroll
    for (int i = 0; i < 16; i++)
        v[i] = srcv[(size_t)(t + 16*i) * 256 + c];
    fft16(v);
    __syncthreads();
#pragma unroll
    for (int k2 = 1; k2 < 16; k2++)
        v[k2] = cmulf(v[k2], tws[t * k2]);
#pragma unroll
    for (int k2 = 0; k2 < 16; k2++)
        sh[t][k2][c] = v[k2];
    __syncthreads();
    float2 u[16];
#pragma unroll
    for (int n1 = 0; n1 < 16; n1++)
        u[n1] = sh[n1][t][c];
    fft16(u);
#pragma unroll
    for (int k1 = 0; k1 < 16; k1++)
        dstv[(size_t)(t + 16*k1) * 65536 + c] = u[k1];
}

// ---------------------------------------------------------------------------
// fw(z) for the self-mirror weight categories.
__device__ __forceinline__ float fwz(int cat, int z) {
    if (cat == 0) return 2.0f;
    if (cat == 2) return 0.0f;
    bool z_mid  = (unsigned)(z - 1) < 127u;
    bool z_self = (z == 0) || (z == 128);
    return z_mid ? 2.0f : (z_self ? 1.0f : 0.0f);
}

// ---------------------------------------------------------------------------
// Pass 3: 512 threads. Warps 0-7 z-FFT direct columns (x,y); warps 8-15
// z-FFT mirrored columns (xm,ym). Both publish spectra to shared in
// z-layout. Direct half then bins PAIRS (z, 256-z) — same shell — merged in
// registers, so the shuffle-aggregation + shared-atomic lane count halves.
// Block = (batch, y=0..128, x-tile of 16).
// ---------------------------------------------------------------------------
__global__ void __launch_bounds__(512, 2)
fft_z_reduce_kernel() {
    __shared__ float2 shD[4096];         // direct: transpose, then z-layout
    __shared__ float2 shM[4096];         // mirror: transpose, then z-layout
    __shared__ float2 tws[256];
    __shared__ float  bins[3 * NUM_SHELLS];
    int tid = threadIdx.x;
    if (tid < 256) tws[tid] = g_tw[tid];
    for (int i = tid; i < 3 * NUM_SHELLS; i += 512) bins[i] = 0.0f;

    int half = tid >> 8;                 // 0 = direct, 1 = mirror
    int wt   = tid & 255;
    int c = wt & 15;
    int t = wt >> 4;
    int bI    = blockIdx.x;
    int batch = bI / 2064;
    int rem   = bI % 2064;
    int y     = rem >> 4;                // 0..128
    int tile  = rem & 15;
    int x  = tile * 16 + c;
    int xm = (256 - x) & 255;
    int ym = (256 - y) & 255;
    const float2* base = g_F2 + (size_t)batch * N_VOX;

    int colx = half ? xm : x;
    int coly = half ? ym : y;
    float2* mySh = half ? shM : shD;

    float2 v[16];
#pragma unroll
    for (int i = 0; i < 16; i++)
        v[i] = base[(size_t)coly * 65536 + (size_t)(t + 16*i) * 256 + colx];
    fft16(v);
    __syncthreads();                     // #1: tws + bins ready
#pragma unroll
    for (int k2 = 1; k2 < 16; k2++)
        v[k2] = cmulf(v[k2], tws[t * k2]);
#pragma unroll
    for (int k2 = 0; k2 < 16; k2++)
        mySh[(t * 16 + k2) * 16 + c] = v[k2];
    __syncthreads();                     // #2: transpose data ready
    float2 R[16];
#pragma unroll
    for (int n1 = 0; n1 < 16; n1++)
        R[n1] = mySh[(n1 * 16 + t) * 16 + c];
    fft16(R);                            // R[k1] = Fz(col, z = t + 16*k1)
    __syncthreads();                     // #3: transpose reads done
    // publish BOTH spectra in z-layout: sh[z*16 + c] = Fz(col, z)
#pragma unroll
    for (int k1 = 0; k1 < 16; k1++)
        mySh[(t + 16*k1) * 16 + c] = R[k1];
    __syncthreads();                     // #4: z-layouts ready

    if (!half) {
        int fx = (x < 128) ? x : x - 256;
        int fy = (y < 128) ? y : y - 256;
        int rxy = fx*fx + fy*fy;
        bool y_mid  = (unsigned)(y - 1) < 127u;
        bool x_mid  = (unsigned)(x - 1) < 127u;
        bool x_self = (x == 0) || (x == 128);
        int cat = (y_mid || x_mid) ? 0 : (x_self ? 1 : 2);

        const unsigned FULL = 0xffffffffu;
        int lpos = tid & 15;

        // paired iterations: z = t + 16*k1 in [0,127], partner zm = 256-z
#pragma unroll
        for (int k1 = 0; k1 < 8; k1++) {
            int z  = t + 16*k1;
            int zm = 256 - z;            // 129..256; z==0 -> 256 (self, w2=0)
            int zmw = zm & 255;
            // voxel (x,y,z): P = Fz(x,y,z), Q = Fz(xm,ym,zm)
            float2 P  = R[k1];
            float2 Q  = shM[zmw * 16 + c];
            // voxel (x,y,zm): P' = Fz(x,y,zm), Q' = Fz(xm,ym,z)
            float2 Pp = shD[zmw * 16 + c];
            float2 Qp = shM[z * 16 + c];

            float w1 = fwz(cat, z);
            float w2 = (z == 0) ? 0.0f : fwz(cat, zm);

            float Fxr = P.x + Pp.x;  // wait—unpack is per-voxel; do separately
            // voxel z unpack: uses P and Q
            float xr1 = P.x + Q.x,  xi1 = P.y - Q.y;    // 2*Fx
            float yr1 = P.y + Q.y,  yi1 = Q.x - P.x;    // 2*Fy
            // voxel zm unpack: P'=Fz(k'), Q'=Fz(-k') with k' at z=zm
            float xr2 = Pp.x + Qp.x, xi2 = Pp.y - Qp.y;
            float yr2 = Pp.y + Qp.y, yi2 = Qp.x - Pp.x;
            (void)Fxr;

            int fz = (z < 128) ? z : z - 256;   // here z<=127 so fz=z... keep general
            int bin = (int)sqrtf((float)(rxy + fz*fz));
            float nn = w1*(xr1*yr1 + xi1*yi1) + w2*(xr2*yr2 + xi2*yi2);
            float pp = w1*(xr1*xr1 + xi1*xi1) + w2*(xr2*xr2 + xi2*xi2);
            float qq = w1*(yr1*yr1 + yi1*yi1) + w2*(yr2*yr2 + yi2*yi2);

            // run-aggregation within each 16-lane segment (bin monotone in x)
#pragma unroll
            for (int off = 1; off < 16; off <<= 1) {
                int   ob = __shfl_down_sync(FULL, bin, off);
                float on = __shfl_down_sync(FULL, nn,  off);
                float op = __shfl_down_sync(FULL, pp,  off);
                float oq = __shfl_down_sync(FULL, qq,  off);
                if (lpos + off < 16 && ob == bin) { nn += on; pp += op; qq += oq; }
            }
            int pb = __shfl_up_sync(FULL, bin, 1);
            if (lpos == 0 || pb != bin) {
                atomicAdd(&bins[bin],                nn);
                atomicAdd(&bins[NUM_SHELLS   + bin], pp);
                atomicAdd(&bins[2*NUM_SHELLS + bin], qq);
            }
        }

        // z = 128 plane: handled by the t==0 segment (warp 0, lanes 0-15).
        if (t == 0) {
            const unsigned M16 = 0x0000ffffu;
            float2 P  = shD[128 * 16 + c];     // Fz(x,y,128)
            float2 Q  = shM[128 * 16 + c];     // Fz(xm,ym,128)
            float xr1 = P.x + Q.x,  xi1 = P.y - Q.y;
            float yr1 = P.y + Q.y,  yi1 = Q.x - P.x;
            float w = fwz(cat, 128);           // cat0->2, cat1->1, cat2->0
            int bin = (int)sqrtf((float)(rxy + 128*128));
            float nn = w*(xr1*yr1 + xi1*yi1);
            float pp = w*(xr1*xr1 + xi1*xi1);
            float qq = w*(yr1*yr1 + yi1*yi1);
#pragma unroll
            for (int off = 1; off < 16; off <<= 1) {
                int   ob = __shfl_down_sync(M16, bin, off);
                float on = __shfl_down_sync(M16, nn,  off);
                float op = __shfl_down_sync(M16, pp,  off);
                float oq = __shfl_down_sync(M16, qq,  off);
                if (lpos + off < 16 && ob == bin) { nn += on; pp += op; qq += oq; }
            }
            int pb = __shfl_up_sync(M16, bin, 1);
            if (lpos == 0 || pb != bin) {
                atomicAdd(&bins[bin],                nn);
                atomicAdd(&bins[NUM_SHELLS   + bin], pp);
                atomicAdd(&bins[2*NUM_SHELLS + bin], qq);
            }
        }
    }
    __syncthreads();                     // #5: bins complete
    float* acc = g_acc + batch * 3 * NUM_SHELLS;
    for (int i = tid; i < 3 * NUM_SHELLS; i += 512)
        atomicAdd(&acc[i], bins[i]);
}

// ---------------------------------------------------------------------------
__global__ void final_kernel(float* __restrict__ out) {
    __shared__ float red[256];
    int tid = threadIdx.x;
    float s = 0.0f;
    for (int i = tid; i < 2 * NUM_SHELLS; i += 256) {
        int bt = i / NUM_SHELLS;
        int sh_ = i % NUM_SHELLS;
        const float* acc = g_acc + bt * 3 * NUM_SHELLS;
        float num = acc[sh_];
        float px  = acc[NUM_SHELLS + sh_];
        float py  = acc[2*NUM_SHELLS + sh_];
        s += num / sqrtf(px * py + 1e-8f);
    }
    red[tid] = s;
    __syncthreads();
    for (int o = 128; o > 0; o >>= 1) {
        if (tid < o) red[tid] += red[tid + o];
        __syncthreads();
    }
    if (tid == 0) out[0] = red[0] / (2.0f * NUM_SHELLS);
}

// ---------------------------------------------------------------------------
extern "C" void kernel_launch(void* const* d_in, const int* in_sizes, int n_in,
                              void* d_out, int out_size) {
    const float* X = (const float*)d_in[0];
    const float* Y = (const float*)d_in[1];

    init_kernel<<<1, 256>>>();
    fft_x_kernel<<<8192, 256>>>(X, Y);      // 2 packed vols * 65536 lines / 16
    fft_y_kernel<<<8192, 256>>>();          // 2 vols * 256 z * 16 tiles
    fft_z_reduce_kernel<<<4128, 512>>>();   // 2 batches * 129 y * 16 tiles
    final_kernel<<<1, 256>>>((float*)d_out);
}